// round 4
// baseline (speedup 1.0000x reference)
#include <cuda_runtime.h>

#define BB    64
#define WW    64
#define FNSEQ 8192
#define NTR   8201
#define NTP   8320
#define NMD   16
#define NSPL  10
#define TRG   832
#define TCA   32

__device__ float g_v0[BB * WW * NTP];
__device__ float g_v1[BB * WW * NTP];
__device__ float g_basis[NTP * 32];
__device__ float g_fpart[NSPL * BB * WW * 32];
__device__ float g_ab[BB * 32 * WW];

__device__ __forceinline__ float gelu_f(float x) {
    return 0.5f * x * (1.0f + erff(x * 0.70710678118654752f));
}

#define FMA16(A, B)                             \
    acc[0][0] = fmaf((A).x, (B).x, acc[0][0]);  \
    acc[0][1] = fmaf((A).x, (B).y, acc[0][1]);  \
    acc[0][2] = fmaf((A).x, (B).z, acc[0][2]);  \
    acc[0][3] = fmaf((A).x, (B).w, acc[0][3]);  \
    acc[1][0] = fmaf((A).y, (B).x, acc[1][0]);  \
    acc[1][1] = fmaf((A).y, (B).y, acc[1][1]);  \
    acc[1][2] = fmaf((A).y, (B).z, acc[1][2]);  \
    acc[1][3] = fmaf((A).y, (B).w, acc[1][3]);  \
    acc[2][0] = fmaf((A).z, (B).x, acc[2][0]);  \
    acc[2][1] = fmaf((A).z, (B).y, acc[2][1]);  \
    acc[2][2] = fmaf((A).z, (B).z, acc[2][2]);  \
    acc[2][3] = fmaf((A).z, (B).w, acc[2][3]);  \
    acc[3][0] = fmaf((A).w, (B).x, acc[3][0]);  \
    acc[3][1] = fmaf((A).w, (B).y, acc[3][1]);  \
    acc[3][2] = fmaf((A).w, (B).z, acc[3][2]);  \
    acc[3][3] = fmaf((A).w, (B).w, acc[3][3]);

__global__ void k_basis() {
    int t = blockIdx.x * 128 + threadIdx.x;
    if (t >= NTP) return;
#pragma unroll
    for (int k = 0; k < NMD; k++) {
        int r = (k * t) % NTR;
        float ang = (float)((double)r * (6.283185307179586 / (double)NTR));
        float s, c;
        sincosf(ang, &s, &c);
        g_basis[t * 32 + k] = c;
        g_basis[t * 32 + NMD + k] = s;
    }
}

__global__ void k_lift(const float* __restrict__ x,
                       const float* __restrict__ lw,
                       const float* __restrict__ lb) {
    int b = blockIdx.x;
    int t = blockIdx.y * 128 + threadIdx.x;
    if (t >= NTP) return;
    if (t >= NTR) {
#pragma unroll 4
        for (int i = 0; i < WW; i++) g_v1[(b * WW + i) * NTP + t] = 0.0f;
    }
    if (t >= FNSEQ) {
#pragma unroll 4
        for (int i = 0; i < WW; i++) g_v0[(b * WW + i) * NTP + t] = 0.0f;
        return;
    }
    float x0 = x[(b * FNSEQ + t) * 2 + 0];
    float x1 = x[(b * FNSEQ + t) * 2 + 1];
#pragma unroll 4
    for (int i = 0; i < WW; i++) {
        g_v0[(b * WW + i) * NTP + t] =
            fmaf(x0, __ldg(&lw[i]), fmaf(x1, __ldg(&lw[WW + i]), __ldg(&lb[i])));
    }
}

// forward restricted DFT partials: F[b,i,k] over t-split s
__global__ void __launch_bounds__(128) k_fwd(int src) {
    const float* __restrict__ vin = src ? g_v1 : g_v0;
    __shared__ __align__(16) float vsT[TCA][WW + 4];
    __shared__ __align__(16) float bsS[TCA][32];
    int b = blockIdx.x, s = blockIdx.y, tid = threadIdx.x;
    int ti = tid & 15, tk = tid >> 4;
    int i0 = ti * 4, k0 = tk * 4;
    float acc[4][4] = {};
    const int tbeg = s * TRG;
    for (int tc = 0; tc < TRG; tc += TCA) {
        int tbase = tbeg + tc;
#pragma unroll
        for (int r = 0; r < 16; r++) {
            int idx = tid + 128 * r;
            int i = idx >> 5, tt = idx & 31;
            vsT[tt][i] = vin[(b * WW + i) * NTP + tbase + tt];
        }
#pragma unroll
        for (int r = 0; r < 2; r++) {
            int idx = tid + 128 * r;
            ((float4*)bsS)[idx] = ((const float4*)(g_basis + tbase * 32))[idx];
        }
        __syncthreads();
#pragma unroll
        for (int tt = 0; tt < TCA; tt++) {
            float4 vv = *(const float4*)&vsT[tt][i0];
            float4 bb = *(const float4*)&bsS[tt][k0];
            FMA16(vv, bb);
        }
        __syncthreads();
    }
    float* fp = g_fpart + (size_t)(s * BB + b) * WW * 32;
#pragma unroll
    for (int a = 0; a < 4; a++)
        *(float4*)&fp[(i0 + a) * 32 + k0] =
            make_float4(acc[a][0], acc[a][1], acc[a][2], acc[a][3]);
}

// mode mixing + irfft-coefficient fold
__global__ void __launch_bounds__(1024) k_mix(const float* __restrict__ kr,
                                              const float* __restrict__ ki) {
    __shared__ float Fs[WW][32];
    int b = blockIdx.x, tid = threadIdx.x;
#pragma unroll
    for (int r = 0; r < 2; r++) {
        int idx = tid + 1024 * r;
        float sum = 0.f;
#pragma unroll
        for (int s = 0; s < NSPL; s++)
            sum += g_fpart[(size_t)(s * BB + b) * WW * 32 + idx];
        ((float*)Fs)[idx] = sum;
    }
    __syncthreads();
    int k = tid & 15, o = tid >> 4;
    float ck = (k == 0) ? (1.0f / (float)NTR) : (2.0f / (float)NTR);
    float pr = 0.f, pi = 0.f;
#pragma unroll 4
    for (int i = 0; i < WW; i++) {
        float fr = Fs[i][k];
        float fs = Fs[i][NMD + k];  // Fi = -fs
        float krv = __ldg(&kr[(i * WW + o) * NMD + k]);
        float kiv = __ldg(&ki[(i * WW + o) * NMD + k]);
        pr = fmaf(fr, krv, fmaf(fs, kiv, pr));
        pi = fmaf(fr, kiv, fmaf(-fs, krv, pi));
    }
    g_ab[(b * 32 + k) * WW + o]       =  ck * pr;   // cos coef
    g_ab[(b * 32 + NMD + k) * WW + o] = -ck * pi;   // sin coef
}

// fused inverse DFT + channel conv + bias + GELU
__global__ void __launch_bounds__(256) k_pt(int src,
                                            const float* __restrict__ cw,
                                            const float* __restrict__ cb) {
    const float* __restrict__ vin  = src ? g_v1 : g_v0;
    float* __restrict__       vout = src ? g_v0 : g_v1;
    __shared__ __align__(16) float vs[WW][64];
    __shared__ __align__(16) float cwT[WW * 64];
    __shared__ __align__(16) float bsT[32 * 64];
    __shared__ __align__(16) float abS[32][WW];
    int b = blockIdx.x;
    int t0 = blockIdx.y * 64;
    int tid = threadIdx.x;
#pragma unroll
    for (int r = 0; r < 4; r++) {
        int idx = tid + 256 * r;
        int i = idx >> 4, tq = idx & 15;
        ((float4*)&vs[i][0])[tq] =
            *(const float4*)&vin[(b * WW + i) * NTP + t0 + tq * 4];
    }
#pragma unroll
    for (int r = 0; r < 16; r++) {
        int idx = tid + 256 * r;  // cw is [o][i]
        int o = idx >> 6, i = idx & 63;
        cwT[i * 64 + ((((o >> 2) ^ (i & 15)) << 2) | (o & 3))] = cw[idx];
    }
#pragma unroll
    for (int r = 0; r < 8; r++) {
        int idx = tid + 256 * r;  // basis is [t][kk]
        int t = idx >> 5, kk = idx & 31;
        bsT[kk * 64 + ((((t >> 2) ^ (kk & 15)) << 2) | (t & 3))] =
            g_basis[(t0 + t) * 32 + kk];
    }
#pragma unroll
    for (int r = 0; r < 2; r++) {
        int idx = tid + 256 * r;
        ((float4*)abS)[idx] = ((const float4*)(g_ab + b * 32 * WW))[idx];
    }
    __syncthreads();

    int to = tid & 15, tt = tid >> 4;
    int o0 = to * 4, tq0 = tt * 4;
    float acc[4][4];
#pragma unroll
    for (int a = 0; a < 4; a++) {
        float c = __ldg(&cb[o0 + a]);
        acc[a][0] = c; acc[a][1] = c; acc[a][2] = c; acc[a][3] = c;
    }
#pragma unroll 8
    for (int i = 0; i < WW; i++) {
        float4 cv = *(const float4*)&cwT[i * 64 + ((to ^ (i & 15)) << 2)];
        float4 vv = *(const float4*)&vs[i][tq0];
        FMA16(cv, vv);
    }
#pragma unroll 8
    for (int kk = 0; kk < 32; kk++) {
        float4 av = *(const float4*)&abS[kk][o0];
        float4 bv = *(const float4*)&bsT[kk * 64 + ((tt ^ (kk & 15)) << 2)];
        FMA16(av, bv);
    }
#pragma unroll
    for (int a = 0; a < 4; a++) {
        float4 g;
        g.x = gelu_f(acc[a][0]);
        g.y = gelu_f(acc[a][1]);
        g.z = gelu_f(acc[a][2]);
        g.w = gelu_f(acc[a][3]);
        size_t base = (size_t)(b * WW + o0 + a) * NTP + t0 + tq0;
        if (t0 + tq0 + 3 < NTR) {
            *(float4*)&vout[base] = g;
        } else {
            if (t0 + tq0 + 0 < NTR) vout[base + 0] = g.x;
            if (t0 + tq0 + 1 < NTR) vout[base + 1] = g.y;
            if (t0 + tq0 + 2 < NTR) vout[base + 2] = g.z;
            if (t0 + tq0 + 3 < NTR) vout[base + 3] = g.w;
        }
    }
}

// final projection: out = gelu(v @ pw1 + b1) @ pw2 + b2
__global__ void __launch_bounds__(256) k_proj(const float* __restrict__ pw1,
                                              const float* __restrict__ pb1,
                                              const float* __restrict__ pw2,
                                              const float* __restrict__ pb2,
                                              float* __restrict__ out) {
    __shared__ __align__(16) float vs[WW][64];
    __shared__ __align__(16) float pw1s[WW][128];
    int b = blockIdx.x;
    int t0 = blockIdx.y * 64;
    int tid = threadIdx.x;
#pragma unroll
    for (int r = 0; r < 4; r++) {
        int idx = tid + 256 * r;
        int i = idx >> 4, tq = idx & 15;
        ((float4*)&vs[i][0])[tq] =
            *(const float4*)&g_v1[(b * WW + i) * NTP + t0 + tq * 4];
    }
#pragma unroll
    for (int r = 0; r < 8; r++) {
        int idx = tid + 256 * r;
        ((float4*)pw1s)[idx] = ((const float4*)pw1)[idx];
    }
    __syncthreads();

    int tj = tid & 15, tt = tid >> 4;
    int j0 = tj * 8, tr0 = tt * 4;
    float acc[4][8] = {};
#pragma unroll 4
    for (int i = 0; i < WW; i++) {
        float4 vv = *(const float4*)&vs[i][tr0];
        float4 p0 = *(const float4*)&pw1s[i][j0];
        float4 p1 = *(const float4*)&pw1s[i][j0 + 4];
        float va[4] = {vv.x, vv.y, vv.z, vv.w};
        float pc[8] = {p0.x, p0.y, p0.z, p0.w, p1.x, p1.y, p1.z, p1.w};
#pragma unroll
        for (int a = 0; a < 4; a++)
#pragma unroll
            for (int c = 0; c < 8; c++)
                acc[a][c] = fmaf(va[a], pc[c], acc[a][c]);
    }
    float s[4] = {};
#pragma unroll
    for (int c = 0; c < 8; c++) {
        float b1 = __ldg(&pb1[j0 + c]);
        float w2 = __ldg(&pw2[j0 + c]);
#pragma unroll
        for (int a = 0; a < 4; a++)
            s[a] = fmaf(gelu_f(acc[a][c] + b1), w2, s[a]);
    }
#pragma unroll
    for (int m = 8; m >= 1; m >>= 1)
#pragma unroll
        for (int a = 0; a < 4; a++)
            s[a] += __shfl_xor_sync(0xffffffffu, s[a], m);
    if (tj == 0) {
        float b2 = __ldg(&pb2[0]);
#pragma unroll
        for (int a = 0; a < 4; a++)
            out[b * FNSEQ + t0 + tr0 + a] = s[a] + b2;
    }
}

extern "C" void kernel_launch(void* const* d_in, const int* in_sizes, int n_in,
                              void* d_out, int out_size) {
    const float* x   = (const float*)d_in[0];
    const float* lw  = (const float*)d_in[1];
    const float* lb  = (const float*)d_in[2];
    const float* kr  = (const float*)d_in[3];
    const float* ki  = (const float*)d_in[4];
    const float* cw  = (const float*)d_in[5];
    const float* cb  = (const float*)d_in[6];
    const float* pw1 = (const float*)d_in[7];
    const float* pb1 = (const float*)d_in[8];
    const float* pw2 = (const float*)d_in[9];
    const float* pb2 = (const float*)d_in[10];
    float* out = (float*)d_out;

    k_basis<<<(NTP + 127) / 128, 128>>>();
    k_lift<<<dim3(BB, (NTP + 127) / 128), 128>>>(x, lw, lb);
    for (int l = 0; l < 5; l++) {
        int src = l & 1;
        k_fwd<<<dim3(BB, NSPL), 128>>>(src);
        k_mix<<<BB, 1024>>>(kr + l * WW * WW * NMD, ki + l * WW * WW * NMD);
        k_pt<<<dim3(BB, NTP / 64), 256>>>(src, cw + l * WW * WW, cb + l * WW);
    }
    k_proj<<<dim3(BB, FNSEQ / 64), 256>>>(pw1, pb1, pw2, pb2, out);
}